// round 14
// baseline (speedup 1.0000x reference)
#include <cuda_runtime.h>

#define BN   4
#define CIN  64
#define COUT 64
#define HH   128
#define WW   128
#define HW   (HH * WW)
#define K2q  9
#define OFFC 18

// Intermediate offset field scratch (no cudaMalloc allowed).
__device__ float g_offset[BN * OFFC * HW];

typedef unsigned long long ull;

// ---- packed f32x2 helpers --------------------------------------------------
__device__ __forceinline__ ull fma2(ull a, ull b, ull c) {
    ull d;
    asm("fma.rn.f32x2 %0, %1, %2, %3;" : "=l"(d) : "l"(a), "l"(b), "l"(c));
    return d;
}
__device__ __forceinline__ ull packs(float s) {   // {s, s}
    ull r; unsigned u = __float_as_uint(s);
    asm("mov.b64 %0, {%1, %1};" : "=l"(r) : "r"(u));
    return r;
}
__device__ __forceinline__ ull packf(float lo, float hi) {
    ull r;
    asm("mov.b64 %0, {%1, %2};" : "=l"(r)
        : "r"(__float_as_uint(lo)), "r"(__float_as_uint(hi)));
    return r;
}
__device__ __forceinline__ void unpackf(ull v, float& lo, float& hi) {
    unsigned a, b;
    asm("mov.b64 {%0, %1}, %2;" : "=r"(a), "=r"(b) : "l"(v));
    lo = __uint_as_float(a); hi = __uint_as_float(b);
}

// ============================================================================
// Kernel 1: plain 3x3 conv 64 -> 18, pad 1. 16x16 pixel tile per CTA,
// 18x18 smem x-tile (halo 1, zero-fill = implicit pad), double buffered.
// 9 packed f32x2 accumulators (18 channels).
// ============================================================================
#define T1   16
#define TS1  18
#define TP1  19

__global__ __launch_bounds__(256)
void offset_conv_kernel(const float* __restrict__ x,
                        const float* __restrict__ w,     // [18][64][3][3]
                        const float* __restrict__ bias)  // [18]
{
    __shared__ __align__(16) float ws[CIN * K2q * OFFC];  // [cq][co] 41472 B
    __shared__ __align__(16) float tb[2][TS1 * TP1];

    const int tid = threadIdx.x;
    for (int i = tid; i < CIN * K2q * OFFC; i += 256) {
        int cq = i / OFFC, co = i - cq * OFFC;
        ws[i] = w[co * (CIN * K2q) + cq];
    }

    const int bx  = blockIdx.x;
    const int b   = bx >> 6;
    const int t   = bx & 63;
    const int ty0 = (t >> 3) * T1, tx0 = (t & 7) * T1;
    const int ry0 = ty0 - 1, cx0 = tx0 - 1;
    const int ty  = tid >> 4, tx = tid & 15;
    const int ho  = ty0 + ty, wo = tx0 + tx;
    const int hw  = ho * WW + wo;
    const float* xb = x + (size_t)b * CIN * HW;

    // initial tile (c = 0), zero-filled outside image
    for (int i = tid; i < TS1 * TS1; i += 256) {
        int r = i / TS1, cl = i - r * TS1;
        int gy = ry0 + r, gx = cx0 + cl;
        float v = 0.f;
        if ((unsigned)gy < (unsigned)HH && (unsigned)gx < (unsigned)WW)
            v = __ldg(xb + gy * WW + gx);
        tb[0][r * TP1 + cl] = v;
    }
    __syncthreads();

    ull acc[9];
#pragma unroll
    for (int j = 0; j < 9; j++) acc[j] = packf(bias[2 * j], bias[2 * j + 1]);

#pragma unroll 1
    for (int c = 0; c < CIN; c++) {
        // prefetch channel c+1 into registers
        float p0 = 0.f, p1 = 0.f;
        if (c < CIN - 1) {
            const float* xc = xb + (c + 1) * HW;
            {
                int i = tid, r = i / TS1, cl = i - r * TS1;
                int gy = ry0 + r, gx = cx0 + cl;
                if ((unsigned)gy < (unsigned)HH && (unsigned)gx < (unsigned)WW)
                    p0 = __ldg(xc + gy * WW + gx);
            }
            if (tid < TS1 * TS1 - 256) {
                int i = tid + 256, r = i / TS1, cl = i - r * TS1;
                int gy = ry0 + r, gx = cx0 + cl;
                if ((unsigned)gy < (unsigned)HH && (unsigned)gx < (unsigned)WW)
                    p1 = __ldg(xc + gy * WW + gx);
            }
        }

        const float* tc = tb[c & 1];
#pragma unroll
        for (int kh = 0; kh < 3; kh++) {
#pragma unroll
            for (int kw = 0; kw < 3; kw++) {
                float v = tc[(ty + kh) * TP1 + (tx + kw)];
                ull v2 = packs(v);
                const ull* wp = (const ull*)(ws + (c * K2q + kh * 3 + kw) * OFFC);
#pragma unroll
                for (int j = 0; j < 9; j++) acc[j] = fma2(v2, wp[j], acc[j]);
            }
        }

        if (c < CIN - 1) {
            float* nb = tb[(c + 1) & 1];
            { int i = tid, r = i / TS1, cl = i - r * TS1; nb[r * TP1 + cl] = p0; }
            if (tid < TS1 * TS1 - 256) {
                int i = tid + 256, r = i / TS1, cl = i - r * TS1;
                nb[r * TP1 + cl] = p1;
            }
        }
        __syncthreads();
    }

    float* ob = g_offset + (size_t)b * OFFC * HW;
#pragma unroll
    for (int j = 0; j < 9; j++) {
        float lo, hi; unpackf(acc[j], lo, hi);
        ob[(2 * j) * HW + hw]     = lo;
        ob[(2 * j + 1) * HW + hw] = hi;
    }
}

// ============================================================================
// Kernel 2: deformable conv. 16x16 pixel tile per CTA, 24x24 smem x-tile
// (halo 4) per channel, double buffered; bilinear taps precomputed per pixel;
// warp-uniform fast path (all taps in-tile -> pure LDS) with clamped-LDG
// fallback. 32 packed f32x2 output accumulators; weights transposed in smem.
// ============================================================================
#define T2   16
#define HALO 4
#define TS   24
#define TP   25

__global__ __launch_bounds__(256, 1)
void deform_conv_kernel(const float* __restrict__ x,
                        const float* __restrict__ w,     // [64][64*9]
                        const float* __restrict__ bias,  // [64]
                        float* __restrict__ out)
{
    extern __shared__ __align__(16) float smem[];
    float* ws  = smem;                       // [576][64] = 147456 B
    float* tbA = smem + CIN * K2q * COUT;    // 600 floats
    float* tbB = tbA + TS * TP;              // 600 floats

    const int tid = threadIdx.x;
    for (int i = tid; i < CIN * K2q * COUT; i += 256) {
        int cq = i >> 6, o = i & 63;
        ws[i] = w[o * (CIN * K2q) + cq];
    }

    const int bx  = blockIdx.x;
    const int b   = bx >> 6;
    const int t   = bx & 63;
    const int ty0 = (t >> 3) * T2, tx0 = (t & 7) * T2;
    const int ry0 = ty0 - HALO, cx0 = tx0 - HALO;
    const int ty  = tid >> 4, tx = tid & 15;
    const int ho  = ty0 + ty, wo = tx0 + tx;
    const int hw  = ho * WW + wo;

    const float* xb   = x + (size_t)b * CIN * HW;
    const float* offb = g_offset + (size_t)b * OFFC * HW;

    // ---- precompute 9 bilinear taps (weights + tile-local base index) ----
    float4 tw[9];
    int    tsi[9];
    bool   allin = true;
#pragma unroll
    for (int q = 0; q < 9; q++) {
        float dy = offb[(2 * q) * HW + hw];
        float dx = offb[(2 * q + 1) * HW + hw];
        int kh = q / 3, kw = q - kh * 3;
        float py = (float)(ho - 1 + kh) + dy;
        float px = (float)(wo - 1 + kw) + dx;
        float y0f = floorf(py), x0f = floorf(px);
        int y0 = (int)y0f, x0 = (int)x0f;
        float wy1 = py - y0f, wx1 = px - x0f;
        float wy0 = 1.f - wy1, wx0 = 1.f - wx1;
        bool vy0 = (unsigned)y0 < (unsigned)HH;
        bool vy1 = (unsigned)(y0 + 1) < (unsigned)HH;
        bool vx0 = (unsigned)x0 < (unsigned)WW;
        bool vx1 = (unsigned)(x0 + 1) < (unsigned)WW;
        tw[q].x = (vy0 && vx0) ? wy0 * wx0 : 0.f;
        tw[q].y = (vy0 && vx1) ? wy0 * wx1 : 0.f;
        tw[q].z = (vy1 && vx0) ? wy1 * wx0 : 0.f;
        tw[q].w = (vy1 && vx1) ? wy1 * wx1 : 0.f;
        int ly = y0 - ry0, lx = x0 - cx0;
        bool in = (ly >= 0) && (ly <= TS - 2) && (lx >= 0) && (lx <= TS - 2);
        tsi[q] = in ? (ly * TP + lx) : -1;
        allin &= in;
    }
    unsigned mask = __ballot_sync(0xffffffffu, allin);
    const bool warp_fast = (mask == 0xffffffffu);

    // ---- initial tile (c = 0) ----
    for (int i = tid; i < TS * TS; i += 256) {
        int r = i / TS, cl = i - r * TS;
        int gy = ry0 + r, gx = cx0 + cl;
        float v = 0.f;
        if ((unsigned)gy < (unsigned)HH && (unsigned)gx < (unsigned)WW)
            v = __ldg(xb + gy * WW + gx);
        tbA[r * TP + cl] = v;
    }
    __syncthreads();

    ull acc[32];
#pragma unroll
    for (int j = 0; j < 32; j++) acc[j] = packf(bias[2 * j], bias[2 * j + 1]);

#pragma unroll 1
    for (int c = 0; c < CIN; c++) {
        float* tcur = (c & 1) ? tbB : tbA;
        float* tnxt = (c & 1) ? tbA : tbB;

        // prefetch channel c+1 (registers first -> overlap with compute)
        float p0 = 0.f, p1 = 0.f, p2 = 0.f;
        if (c < CIN - 1) {
            const float* xc = xb + (c + 1) * HW;
            {
                int i = tid, r = i / TS, cl = i - r * TS;
                int gy = ry0 + r, gx = cx0 + cl;
                if ((unsigned)gy < (unsigned)HH && (unsigned)gx < (unsigned)WW)
                    p0 = __ldg(xc + gy * WW + gx);
            }
            {
                int i = tid + 256, r = i / TS, cl = i - r * TS;
                int gy = ry0 + r, gx = cx0 + cl;
                if ((unsigned)gy < (unsigned)HH && (unsigned)gx < (unsigned)WW)
                    p1 = __ldg(xc + gy * WW + gx);
            }
            if (tid < TS * TS - 512) {
                int i = tid + 512, r = i / TS, cl = i - r * TS;
                int gy = ry0 + r, gx = cx0 + cl;
                if ((unsigned)gy < (unsigned)HH && (unsigned)gx < (unsigned)WW)
                    p2 = __ldg(xc + gy * WW + gx);
            }
        }

        if (warp_fast) {
            // all taps resolved in-tile: pure LDS sampling
#pragma unroll
            for (int q = 0; q < 9; q++) {
                int si = tsi[q];
                float s = tw[q].x * tcur[si]          + tw[q].y * tcur[si + 1]
                        + tw[q].z * tcur[si + TP]     + tw[q].w * tcur[si + TP + 1];
                ull s2 = packs(s);
                const ulonglong2* wp =
                    (const ulonglong2*)(ws + (c * K2q + q) * COUT);
#pragma unroll
                for (int j = 0; j < 16; j++) {
                    ulonglong2 wv = wp[j];
                    acc[2 * j]     = fma2(s2, wv.x, acc[2 * j]);
                    acc[2 * j + 1] = fma2(s2, wv.y, acc[2 * j + 1]);
                }
            }
        } else {
            // general path: per-tap in-tile test, clamped global fallback
            const float* xc = xb + c * HW;
#pragma unroll
            for (int q = 0; q < 9; q++) {
                int si = tsi[q];
                float s;
                if (si >= 0) {
                    s = tw[q].x * tcur[si]          + tw[q].y * tcur[si + 1]
                      + tw[q].z * tcur[si + TP]     + tw[q].w * tcur[si + TP + 1];
                } else {
                    float dy = __ldg(offb + (2 * q) * HW + hw);
                    float dx = __ldg(offb + (2 * q + 1) * HW + hw);
                    int kh = q / 3, kw = q - kh * 3;
                    int y0 = (int)floorf((float)(ho - 1 + kh) + dy);
                    int x0 = (int)floorf((float)(wo - 1 + kw) + dx);
                    int yc0 = min(max(y0, 0), HH - 1);
                    int yc1 = min(max(y0 + 1, 0), HH - 1);
                    int xc0i = min(max(x0, 0), WW - 1);
                    int xc1i = min(max(x0 + 1, 0), WW - 1);
                    s = tw[q].x * __ldg(xc + yc0 * WW + xc0i)
                      + tw[q].y * __ldg(xc + yc0 * WW + xc1i)
                      + tw[q].z * __ldg(xc + yc1 * WW + xc0i)
                      + tw[q].w * __ldg(xc + yc1 * WW + xc1i);
                }
                ull s2 = packs(s);
                const ulonglong2* wp =
                    (const ulonglong2*)(ws + (c * K2q + q) * COUT);
#pragma unroll
                for (int j = 0; j < 16; j++) {
                    ulonglong2 wv = wp[j];
                    acc[2 * j]     = fma2(s2, wv.x, acc[2 * j]);
                    acc[2 * j + 1] = fma2(s2, wv.y, acc[2 * j + 1]);
                }
            }
        }

        if (c < CIN - 1) {
            { int i = tid, r = i / TS, cl = i - r * TS; tnxt[r * TP + cl] = p0; }
            { int i = tid + 256, r = i / TS, cl = i - r * TS; tnxt[r * TP + cl] = p1; }
            if (tid < TS * TS - 512) {
                int i = tid + 512, r = i / TS, cl = i - r * TS;
                tnxt[r * TP + cl] = p2;
            }
        }
        __syncthreads();
    }

    float* ob = out + (size_t)b * COUT * HW;
#pragma unroll
    for (int j = 0; j < 32; j++) {
        float lo, hi; unpackf(acc[j], lo, hi);
        ob[(2 * j) * HW + hw]     = lo;
        ob[(2 * j + 1) * HW + hw] = hi;
    }
}

// ---------------------------------------------------------------------------
extern "C" void kernel_launch(void* const* d_in, const int* in_sizes, int n_in,
                              void* d_out, int out_size)
{
    const float* x     = (const float*)d_in[0];  // [4,64,128,128]
    const float* w_off = (const float*)d_in[1];  // [18,64,3,3]
    const float* b_off = (const float*)d_in[2];  // [18]
    const float* w_def = (const float*)d_in[3];  // [64,64,3,3]
    const float* b_def = (const float*)d_in[4];  // [64]
    float* out = (float*)d_out;                  // [4,64,128,128]

    const int smem2 = (CIN * K2q * COUT + 2 * TS * TP) * (int)sizeof(float);
    cudaFuncSetAttribute(deform_conv_kernel,
                         cudaFuncAttributeMaxDynamicSharedMemorySize, smem2);

    offset_conv_kernel<<<BN * 64, 256>>>(x, w_off, b_off);
    deform_conv_kernel<<<BN * 64, 256, smem2>>>(x, w_def, b_def, out);
}

// round 15
// speedup vs baseline: 1.2383x; 1.2383x over previous
#include <cuda_runtime.h>
#include <cstdint>

#define BN   4
#define CIN  64
#define COUT 64
#define HH   128
#define WW   128
#define HW   (HH * WW)
#define K2q  9
#define OFFC 18

// Intermediate offset field scratch (no cudaMalloc allowed).
__device__ float g_offset[BN * OFFC * HW];

typedef unsigned long long ull;

// ---- packed f32x2 helpers --------------------------------------------------
__device__ __forceinline__ ull fma2(ull a, ull b, ull c) {
    ull d;
    asm("fma.rn.f32x2 %0, %1, %2, %3;" : "=l"(d) : "l"(a), "l"(b), "l"(c));
    return d;
}
__device__ __forceinline__ ull packs(float s) {   // {s, s}
    ull r; unsigned u = __float_as_uint(s);
    asm("mov.b64 %0, {%1, %1};" : "=l"(r) : "r"(u));
    return r;
}
__device__ __forceinline__ ull packf(float lo, float hi) {
    ull r;
    asm("mov.b64 %0, {%1, %2};" : "=l"(r)
        : "r"(__float_as_uint(lo)), "r"(__float_as_uint(hi)));
    return r;
}
__device__ __forceinline__ void unpackf(ull v, float& lo, float& hi) {
    unsigned a, b;
    asm("mov.b64 {%0, %1}, %2;" : "=r"(a), "=r"(b) : "l"(v));
    lo = __uint_as_float(a); hi = __uint_as_float(b);
}
__device__ __forceinline__ void cp4(uint32_t dst, const void* src) {
    asm volatile("cp.async.ca.shared.global [%0], [%1], 4;"
                 :: "r"(dst), "l"(src));
}

// ============================================================================
// Kernel 1: plain 3x3 conv 64 -> 18 (unchanged from R14: ~25us, not critical).
// ============================================================================
#define T1   16
#define TS1  18
#define TP1  19

__global__ __launch_bounds__(256)
void offset_conv_kernel(const float* __restrict__ x,
                        const float* __restrict__ w,
                        const float* __restrict__ bias)
{
    __shared__ __align__(16) float ws[CIN * K2q * OFFC];
    __shared__ __align__(16) float tb[2][TS1 * TP1];

    const int tid = threadIdx.x;
    for (int i = tid; i < CIN * K2q * OFFC; i += 256) {
        int cq = i / OFFC, co = i - cq * OFFC;
        ws[i] = w[co * (CIN * K2q) + cq];
    }

    const int bx  = blockIdx.x;
    const int b   = bx >> 6;
    const int t   = bx & 63;
    const int ty0 = (t >> 3) * T1, tx0 = (t & 7) * T1;
    const int ry0 = ty0 - 1, cx0 = tx0 - 1;
    const int ty  = tid >> 4, tx = tid & 15;
    const int ho  = ty0 + ty, wo = tx0 + tx;
    const int hw  = ho * WW + wo;
    const float* xb = x + (size_t)b * CIN * HW;

    for (int i = tid; i < TS1 * TS1; i += 256) {
        int r = i / TS1, cl = i - r * TS1;
        int gy = ry0 + r, gx = cx0 + cl;
        float v = 0.f;
        if ((unsigned)gy < (unsigned)HH && (unsigned)gx < (unsigned)WW)
            v = __ldg(xb + gy * WW + gx);
        tb[0][r * TP1 + cl] = v;
    }
    __syncthreads();

    ull acc[9];
#pragma unroll
    for (int j = 0; j < 9; j++) acc[j] = packf(bias[2 * j], bias[2 * j + 1]);

#pragma unroll 1
    for (int c = 0; c < CIN; c++) {
        float p0 = 0.f, p1 = 0.f;
        if (c < CIN - 1) {
            const float* xc = xb + (c + 1) * HW;
            {
                int i = tid, r = i / TS1, cl = i - r * TS1;
                int gy = ry0 + r, gx = cx0 + cl;
                if ((unsigned)gy < (unsigned)HH && (unsigned)gx < (unsigned)WW)
                    p0 = __ldg(xc + gy * WW + gx);
            }
            if (tid < TS1 * TS1 - 256) {
                int i = tid + 256, r = i / TS1, cl = i - r * TS1;
                int gy = ry0 + r, gx = cx0 + cl;
                if ((unsigned)gy < (unsigned)HH && (unsigned)gx < (unsigned)WW)
                    p1 = __ldg(xc + gy * WW + gx);
            }
        }

        const float* tc = tb[c & 1];
#pragma unroll
        for (int kh = 0; kh < 3; kh++) {
#pragma unroll
            for (int kw = 0; kw < 3; kw++) {
                float v = tc[(ty + kh) * TP1 + (tx + kw)];
                ull v2 = packs(v);
                const ull* wp = (const ull*)(ws + (c * K2q + kh * 3 + kw) * OFFC);
#pragma unroll
                for (int j = 0; j < 9; j++) acc[j] = fma2(v2, wp[j], acc[j]);
            }
        }

        if (c < CIN - 1) {
            float* nb = tb[(c + 1) & 1];
            { int i = tid, r = i / TS1, cl = i - r * TS1; nb[r * TP1 + cl] = p0; }
            if (tid < TS1 * TS1 - 256) {
                int i = tid + 256, r = i / TS1, cl = i - r * TS1;
                nb[r * TP1 + cl] = p1;
            }
        }
        __syncthreads();
    }

    float* ob = g_offset + (size_t)b * OFFC * HW;
#pragma unroll
    for (int j = 0; j < 9; j++) {
        float lo, hi; unpackf(acc[j], lo, hi);
        ob[(2 * j) * HW + hw]     = lo;
        ob[(2 * j + 1) * HW + hw] = hi;
    }
}

// ============================================================================
// Kernel 2: deformable conv as two-phase blocked GEMM.
//   CTA: 16x32 = 512 pixels, 256 threads, grid = 128 (1 wave).
//   Chunk = 4 input channels (K-slice of 36).
//   Phase A: per-pixel bilinear sampling -> s_tile[36][512] in smem.
//   Phase B: GEMM 512x64x36, thread block = 8 px x 16 out, f32x2 accs.
//   x-tile + weight chunk double-buffered via cp.async.
// ============================================================================
#define TH     16
#define TWd    32
#define NPX    512
#define HALO   4
#define XROWS  24          // TH + 2*HALO
#define XCOLS  40          // TWd + 2*HALO
#define XPITCH 41
#define XCH    (XROWS * XPITCH)   // 984
#define XBUF   (4 * XCH)          // 3936
#define WBUF   (36 * 64)          // 2304

// smem float offsets
#define S_S    0                      // s_tile [36*512]  = 18432
#define S_W    18432                  // ws     [2*2304]  =  4608
#define S_X    (S_W + 2 * WBUF)       // x_tile [2*3936]  =  7872
#define S_OFF  (S_X + 2 * XBUF)       // off_s  [18*512]  =  9216
#define S_TOT  (S_OFF + 18 * 512)     // 40128 floats = 160512 B

__device__ __forceinline__ void issue_chunk(int chunk, int buf, int tid,
                                            int ry0, int cx0,
                                            const float* xb, const float* w,
                                            uint32_t smbase)
{
    // x tiles: 4 channels x 24 x 40 = 3840 elements (OOB stays zero)
    const float* xc = xb + (size_t)chunk * 4 * HW;
    const uint32_t xdst = smbase + (S_X + buf * XBUF) * 4;
#pragma unroll
    for (int j = 0; j < 15; j++) {
        int i = tid + j * 256;
        int cc = i / 960, rem = i - cc * 960;
        int row = rem / 40, col = rem - row * 40;
        int gy = ry0 + row, gx = cx0 + col;
        if ((unsigned)gy < (unsigned)HH && (unsigned)gx < (unsigned)WW)
            cp4(xdst + (uint32_t)(cc * XCH + row * XPITCH + col) * 4,
                xc + cc * HW + gy * WW + gx);
    }
    // weights transposed: ws[kk][o] <- w[o][chunk*36 + kk]
    const uint32_t wdst = smbase + (S_W + buf * WBUF) * 4;
#pragma unroll
    for (int j = 0; j < 9; j++) {
        int i = tid + j * 256;
        int kk = i >> 6, o = i & 63;
        cp4(wdst + (uint32_t)i * 4, w + o * 576 + chunk * 36 + kk);
    }
}

__global__ __launch_bounds__(256, 1)
void deform_conv_kernel(const float* __restrict__ x,
                        const float* __restrict__ w,     // [64][576]
                        const float* __restrict__ bias,  // [64]
                        float* __restrict__ out)
{
    extern __shared__ __align__(16) float sm[];
    float* s_tile = sm + S_S;
    float* wsm    = sm + S_W;
    float* x_t    = sm + S_X;
    float* off_s  = sm + S_OFF;
    const uint32_t smbase = (uint32_t)__cvta_generic_to_shared(sm);

    const int tid = threadIdx.x;
    const int bx  = blockIdx.x;
    const int b   = bx >> 5;
    const int t   = bx & 31;                       // 8 x 4 tiles
    const int ty0 = (t >> 2) * TH, tx0 = (t & 3) * TWd;
    const int ry0 = ty0 - HALO,   cx0 = tx0 - HALO;

    const float* xb   = x + (size_t)b * CIN * HW;
    const float* offb = g_offset + (size_t)b * OFFC * HW;

    // zero x tiles (OOB cells persist as zero), stage offsets
    for (int i = tid; i < 2 * XBUF; i += 256) x_t[i] = 0.f;
    for (int i = tid; i < 18 * 512; i += 256) {
        int j = i >> 9, p = i & 511;
        off_s[i] = __ldg(offb + j * HW + (ty0 + (p >> 5)) * WW + tx0 + (p & 31));
    }
    __syncthreads();   // zeros visible before cp.async may overwrite in-bounds

    issue_chunk(0, 0, tid, ry0, cx0, xb, w, smbase);
    asm volatile("cp.async.commit_group;" ::: "memory");
    asm volatile("cp.async.wait_group 0;" ::: "memory");
    __syncthreads();

    const int pg = tid & 63, og = tid >> 6;

    ull acc[64];   // acc[j*8+m]: pixel j (0-3 quadA, 4-7 quadB), out pair m
#pragma unroll
    for (int m = 0; m < 8; m++) {
        ull bv = packf(__ldg(bias + og * 16 + 2 * m),
                       __ldg(bias + og * 16 + 2 * m + 1));
#pragma unroll
        for (int j = 0; j < 8; j++) acc[j * 8 + m] = bv;
    }

#pragma unroll 1
    for (int ch = 0; ch < 16; ch++) {
        const int buf = ch & 1;
        if (ch < 15) {
            issue_chunk(ch + 1, buf ^ 1, tid, ry0, cx0, xb, w, smbase);
            asm volatile("cp.async.commit_group;" ::: "memory");
        }

        // ---------------- Phase A: sampling -> s_tile ----------------
        const float* xt = x_t + buf * XBUF;
#pragma unroll 1
        for (int pp = 0; pp < 2; pp++) {
            const int p  = tid + pp * 256;
            const int ho = ty0 + (p >> 5), wo = tx0 + (p & 31);
#pragma unroll
            for (int q = 0; q < 9; q++) {
                float dy = off_s[(2 * q) * 512 + p];
                float dx = off_s[(2 * q + 1) * 512 + p];
                int kh = q / 3, kw = q - kh * 3;
                float py  = (float)(ho - 1 + kh) + dy;
                float pxf = (float)(wo - 1 + kw) + dx;
                float y0f = floorf(py), x0f = floorf(pxf);
                int y0 = (int)y0f, x0 = (int)x0f;
                float wy1 = py - y0f, wx1 = pxf - x0f;
                float wy0 = 1.f - wy1, wx0 = 1.f - wx1;
                bool vy0 = (unsigned)y0 < (unsigned)HH;
                bool vy1 = (unsigned)(y0 + 1) < (unsigned)HH;
                bool vx0 = (unsigned)x0 < (unsigned)WW;
                bool vx1 = (unsigned)(x0 + 1) < (unsigned)WW;
                float w00 = (vy0 && vx0) ? wy0 * wx0 : 0.f;
                float w01 = (vy0 && vx1) ? wy0 * wx1 : 0.f;
                float w10 = (vy1 && vx0) ? wy1 * wx0 : 0.f;
                float w11 = (vy1 && vx1) ? wy1 * wx1 : 0.f;
                int ly = y0 - ry0, lx = x0 - cx0;

                if ((unsigned)ly < (unsigned)(XROWS - 1) &&
                    (unsigned)lx < (unsigned)(XCOLS - 1)) {
                    const float* bp0 = xt + ly * XPITCH + lx;
#pragma unroll
                    for (int cc = 0; cc < 4; cc++) {
                        const float* bp = bp0 + cc * XCH;
                        float s = w00 * bp[0]       + w01 * bp[1]
                                + w10 * bp[XPITCH]  + w11 * bp[XPITCH + 1];
                        s_tile[(cc * 9 + q) * 512 + p] = s;
                    }
                } else {
                    int yc0 = min(max(y0, 0), HH - 1);
                    int yc1 = min(max(y0 + 1, 0), HH - 1);
                    int xl0 = min(max(x0, 0), WW - 1);
                    int xl1 = min(max(x0 + 1, 0), WW - 1);
                    const float* xg = xb + (size_t)(ch * 4) * HW;
#pragma unroll
                    for (int cc = 0; cc < 4; cc++) {
                        const float* xgc = xg + cc * HW;
                        float s = w00 * __ldg(xgc + yc0 * WW + xl0)
                                + w01 * __ldg(xgc + yc0 * WW + xl1)
                                + w10 * __ldg(xgc + yc1 * WW + xl0)
                                + w11 * __ldg(xgc + yc1 * WW + xl1);
                        s_tile[(cc * 9 + q) * 512 + p] = s;
                    }
                }
            }
        }
        __syncthreads();

        // ---------------- Phase B: 512x64x36 GEMM slice ----------------
        {
            const float* sp = s_tile + 4 * pg;
            const float* wp = wsm + buf * WBUF + og * 16;
#pragma unroll 4
            for (int kk = 0; kk < 36; kk++) {
                float4 sa = *(const float4*)(sp + kk * 512);
                float4 sb = *(const float4*)(sp + kk * 512 + 256);
                const ulonglong2* wq = (const ulonglong2*)(wp + kk * 64);
                ulonglong2 wv0 = wq[0], wv1 = wq[1], wv2 = wq[2], wv3 = wq[3];
                ull wv[8] = { wv0.x, wv0.y, wv1.x, wv1.y,
                              wv2.x, wv2.y, wv3.x, wv3.y };
                ull s2[8] = { packs(sa.x), packs(sa.y), packs(sa.z), packs(sa.w),
                              packs(sb.x), packs(sb.y), packs(sb.z), packs(sb.w) };
#pragma unroll
                for (int j = 0; j < 8; j++)
#pragma unroll
                    for (int m = 0; m < 8; m++)
                        acc[j * 8 + m] = fma2(s2[j], wv[m], acc[j * 8 + m]);
            }
        }

        if (ch < 15) asm volatile("cp.async.wait_group 0;" ::: "memory");
        __syncthreads();
    }

    // ---------------- Epilogue: STG.128 over pixel quads ----------------
    float* ob = out + (size_t)b * COUT * HW;
    const int pA  = 4 * pg;
    const int hwA = (ty0 + (pA >> 5)) * WW + tx0 + (pA & 31);
    const int hwB = hwA + 8 * WW;
#pragma unroll
    for (int m = 0; m < 8; m++) {
        int o0 = og * 16 + 2 * m;
        float a0, a1, b0, b1, c0, c1, d0, d1;
        unpackf(acc[0 * 8 + m], a0, a1); unpackf(acc[1 * 8 + m], b0, b1);
        unpackf(acc[2 * 8 + m], c0, c1); unpackf(acc[3 * 8 + m], d0, d1);
        *(float4*)(ob + (size_t)o0 * HW + hwA)       = make_float4(a0, b0, c0, d0);
        *(float4*)(ob + (size_t)(o0 + 1) * HW + hwA) = make_float4(a1, b1, c1, d1);
        unpackf(acc[4 * 8 + m], a0, a1); unpackf(acc[5 * 8 + m], b0, b1);
        unpackf(acc[6 * 8 + m], c0, c1); unpackf(acc[7 * 8 + m], d0, d1);
        *(float4*)(ob + (size_t)o0 * HW + hwB)       = make_float4(a0, b0, c0, d0);
        *(float4*)(ob + (size_t)(o0 + 1) * HW + hwB) = make_float4(a1, b1, c1, d1);
    }
}

// ---------------------------------------------------------------------------
extern "C" void kernel_launch(void* const* d_in, const int* in_sizes, int n_in,
                              void* d_out, int out_size)
{
    const float* x     = (const float*)d_in[0];  // [4,64,128,128]
    const float* w_off = (const float*)d_in[1];  // [18,64,3,3]
    const float* b_off = (const float*)d_in[2];  // [18]
    const float* w_def = (const float*)d_in[3];  // [64,64,3,3]
    const float* b_def = (const float*)d_in[4];  // [64]
    float* out = (float*)d_out;                  // [4,64,128,128]

    const int smem2 = S_TOT * (int)sizeof(float);  // 160512 B
    cudaFuncSetAttribute(deform_conv_kernel,
                         cudaFuncAttributeMaxDynamicSharedMemorySize, smem2);

    offset_conv_kernel<<<BN * 64, 256>>>(x, w_off, b_off);
    deform_conv_kernel<<<BN * 32, 256, smem2>>>(x, w_def, b_def, out);
}